// round 9
// baseline (speedup 1.0000x reference)
#include <cuda_runtime.h>
#include <cuda_bf16.h>
#include <cstdint>

#define HW 256
#define CHN 32
#define HID 256
#define K1 96
#define SP 104          // row stride (bf16 elems) for P / W1
#define SH 264          // row stride (bf16 elems) for H / W2
#define TM 64           // pixels per tile
#define NTILES 8192
#define NCTAS 148
#define NTH 512

// smem byte offsets (unchanged from r8)
#define OFF_W1H 0
#define OFF_W1M (OFF_W1H + HID*SP*2)
#define OFF_W2H (OFF_W1M + HID*SP*2)
#define OFF_B1  (OFF_W2H + CHN*SH*2)
#define OFF_W2R3 (OFF_B1 + HID*4)
#define OFF_PH  (OFF_W2R3 + HID*4)
#define OFF_PM  (OFF_PH + TM*SP*2)
#define OFF_H   (OFF_PM + TM*SP*2)
#define OFF_C3  (OFF_H + TM*SH*2)
#define OFF_PART OFF_PH
#define OFF_RB  (OFF_C3 + TM*4 + 16)
#define RB_CH   220
#define RB_ROW  72
#define OFF_XC  (OFF_RB + CHN*RB_CH*4)
#define SMEM_TOTAL (OFF_XC + TM*33*4)         // 222736

__device__ float g_x2[8 * CHN * HW * HW];

__device__ __forceinline__ uint32_t smem_u32(const void* p) {
    uint32_t a;
    asm("{ .reg .u64 t; cvta.to.shared.u64 t, %1; cvt.u32.u64 %0, t; }" : "=r"(a) : "l"(p));
    return a;
}
__device__ __forceinline__ void ldm_x4(uint32_t a, uint32_t& r0, uint32_t& r1, uint32_t& r2, uint32_t& r3) {
    asm volatile("ldmatrix.sync.aligned.m8n8.x4.shared.b16 {%0,%1,%2,%3}, [%4];"
                 : "=r"(r0), "=r"(r1), "=r"(r2), "=r"(r3) : "r"(a));
}
__device__ __forceinline__ void ldm_x2(uint32_t a, uint32_t& r0, uint32_t& r1) {
    asm volatile("ldmatrix.sync.aligned.m8n8.x2.shared.b16 {%0,%1}, [%2];"
                 : "=r"(r0), "=r"(r1) : "r"(a));
}
__device__ __forceinline__ void mma16816(float* d, const uint32_t* a, const uint32_t* b) {
    asm volatile("mma.sync.aligned.m16n8k16.row.col.f32.bf16.bf16.f32 "
                 "{%0,%1,%2,%3}, {%4,%5,%6,%7}, {%8,%9}, {%0,%1,%2,%3};"
                 : "+f"(d[0]), "+f"(d[1]), "+f"(d[2]), "+f"(d[3])
                 : "r"(a[0]), "r"(a[1]), "r"(a[2]), "r"(a[3]), "r"(b[0]), "r"(b[1]));
}
__device__ __forceinline__ uint32_t pack2(float lo, float hi) {
    __nv_bfloat162 t = __floats2bfloat162_rn(lo, hi);
    return *(uint32_t*)&t;
}
__device__ __forceinline__ uint32_t pkraw(__nv_bfloat16 lo, __nv_bfloat16 hi) {
    return ((uint32_t)__bfloat16_as_ushort(hi) << 16) | (uint32_t)__bfloat16_as_ushort(lo);
}

// ---------------------------------------------------------------------------
__global__ __launch_bounds__(NTH, 1)
void nca_mma_kernel(const float* __restrict__ x, const float* __restrict__ ru,
                    const float* __restrict__ W1, const float* __restrict__ b1,
                    const float* __restrict__ W2)
{
    extern __shared__ char smem[];
    const uint32_t sbase = smem_u32(smem);
    const int tid = threadIdx.x;
    const int wid = tid >> 5;          // 0..15
    const int l   = tid & 31;

    // ---- one-time: weights into smem
    for (int idx = tid; idx < HID * K1; idx += NTH) {
        int n = idx / K1, k = idx - n * K1;
        float v = W1[idx];
        __nv_bfloat16 h = __float2bfloat16_rn(v);
        float r = v - __bfloat162float(h);
        *(__nv_bfloat16*)(smem + OFF_W1H + (n * SP + k) * 2) = h;
        *(__nv_bfloat16*)(smem + OFF_W1M + (n * SP + k) * 2) = __float2bfloat16_rn(r);
    }
    for (int idx = tid; idx < CHN * HID; idx += NTH) {
        int n = idx >> 8, k = idx & 255;
        *(__nv_bfloat16*)(smem + OFF_W2H + (n * SH + k) * 2) = __float2bfloat16_rn(W2[idx]);
    }
    for (int idx = tid; idx < HID; idx += NTH) {
        ((float*)(smem + OFF_B1))[idx]   = b1[idx];
        ((float*)(smem + OFF_W2R3))[idx] = W2[3 * HID + idx];
    }
    if (tid < TM) ((float*)(smem + OFF_C3))[tid] = 0.f;
    __syncthreads();

    const float* b1f   = (const float*)(smem + OFF_B1);
    const float* w2r3  = (const float*)(smem + OFF_W2R3);
    float*       sC3   = (float*)(smem + OFF_C3);
    float*       sPart = (float*)(smem + OFF_PART);
    const float* rb    = (const float*)(smem + OFF_RB);
    float*       sXC   = (float*)(smem + OFF_XC);

    const int q  = l >> 2;
    const int cb = 2 * (l & 3);

    // ---- tile-invariant prefetch chunk geometry (<=4 chunks/thread) ----
    int pfRow[4], pfCx[4];
    uint32_t pfDst[4], pfChO[4];
    int nPf = 0;
    for (int k = 0; k < 4; ++k) {
        int i = tid + NTH * k;
        if (i < 1728) {
            int ch  = i / 54;
            int rem = i - ch * 54;
            int row = rem / 18;
            int cx  = rem - row * 18;
            pfRow[nPf] = row;
            pfCx[nPf]  = cx;
            pfChO[nPf] = ((uint32_t)ch << 16);
            pfDst[nPf] = sbase + OFF_RB + (uint32_t)(ch * RB_CH + row * RB_ROW + cx * 4) * 4;
            ++nPf;
        }
    }

    auto prefetch = [&](int tile) {
        const int b  = tile >> 10;
        const int rr = tile & 1023;
        const int y  = rr >> 2;
        const int xb = (rr & 3) << 6;
        const float* xim = x + (uint32_t)b * (CHN * HW * HW);
        for (int k = 0; k < nPf; ++k) {
            const int srow = y - 1 + pfRow[k];
            const int px0  = xb - 4 + pfCx[k] * 4;
            const bool ok = (srow >= 0) & (srow < HW) & (px0 >= 0) & (px0 <= HW - 4);
            const float* src = xim + pfChO[k] + ((uint32_t)(srow & 255) << 8) + (px0 & 255);
            const int sz = ok ? 16 : 0;
            asm volatile("cp.async.ca.shared.global [%0], [%1], 16, %2;"
                         :: "r"(pfDst[k]), "l"(src), "r"(sz));
        }
        asm volatile("cp.async.commit_group;" ::: "memory");
    };

    if (blockIdx.x < NTILES) prefetch(blockIdx.x);

    for (int tile = blockIdx.x; tile < NTILES; tile += NCTAS) {
        const int b  = tile >> 10;
        const int rr = tile & 1023;
        const int y  = rr >> 2;
        const int xb = (rr & 3) << 6;

        asm volatile("cp.async.wait_group 0;" ::: "memory");
        __syncthreads();

        // ============ Phase A: perceive (2 channels/warp) ============
        {
            const int c0 = wid * 2;
            uint32_t* pH = (uint32_t*)(smem + OFF_PH);
            uint32_t* pM = (uint32_t*)(smem + OFF_PM);
#pragma unroll
            for (int half = 0; half < 2; ++half) {
                const int pp = l + 32 * half;
                float vv[6];
#pragma unroll
                for (int u = 0; u < 2; ++u) {
                    const int c = c0 + u;
                    const float* r0 = rb + c * RB_CH + (pp + 3);
                    const float* r1 = r0 + RB_ROW;
                    const float* r2 = r1 + RB_ROW;
                    float a00 = r0[0], a01 = r0[1], a02 = r0[2];
                    float a10 = r1[0], a11 = r1[1], a12 = r1[2];
                    float a20 = r2[0], a21 = r2[1], a22 = r2[2];
                    vv[3 * u]     = a11;
                    vv[3 * u + 1] = ((a02 - a00) + 2.f * (a12 - a10) + (a22 - a20)) * 0.125f;
                    vv[3 * u + 2] = ((a20 - a00) + 2.f * (a21 - a01) + (a22 - a02)) * 0.125f;
                    sXC[pp * 33 + c] = a11;
                }
                __nv_bfloat16 h[6];
                uint32_t mw[3];
#pragma unroll
                for (int j = 0; j < 3; ++j) {
                    h[2*j]   = __float2bfloat16_rn(vv[2*j]);
                    h[2*j+1] = __float2bfloat16_rn(vv[2*j+1]);
                    __nv_bfloat16 m0 = __float2bfloat16_rn(vv[2*j]   - __bfloat162float(h[2*j]));
                    __nv_bfloat16 m1 = __float2bfloat16_rn(vv[2*j+1] - __bfloat162float(h[2*j+1]));
                    mw[j] = pkraw(m0, m1);
                }
                const int wofs = pp * 52 + 3 * wid;   // elems 6*wid = words 3*wid
                pH[wofs]     = pkraw(h[0], h[1]);
                pH[wofs + 1] = pkraw(h[2], h[3]);
                pH[wofs + 2] = pkraw(h[4], h[5]);
                pM[wofs]     = mw[0];
                pM[wofs + 1] = mw[1];
                pM[wofs + 2] = mw[2];
            }
        }
        __syncthreads();

        if (tile + NCTAS < NTILES) prefetch(tile + NCTAS);

        // ============ Phase B: GEMM1 (M64 x N256 x K96), 16 warps = 2M x 8N ============
        const int wm = wid >> 3, wn = wid & 7;
        float acc[2][4][4];
#pragma unroll
        for (int i = 0; i < 2; ++i)
#pragma unroll
            for (int j = 0; j < 4; ++j)
#pragma unroll
                for (int e = 0; e < 4; ++e) acc[i][j][e] = 0.f;
        {
            const int gi = l >> 3;
            const int gj = (gi >> 1) * 8 + (l & 7);
            const int gk = (gi & 1) << 3;
            const uint32_t AH = sbase + OFF_PH, AM = sbase + OFF_PM;
            const uint32_t BH = sbase + OFF_W1H, BM = sbase + OFF_W1M;
#pragma unroll
            for (int ks = 0; ks < 6; ++ks) {
                const int k0 = ks * 16;
                const uint32_t aoff = ((wm * 32 + (l & 15)) * SP + k0 + ((l >> 4) << 3)) * 2;
                const uint32_t boff = ((wn * 32 + gj) * SP + k0 + gk) * 2;
                uint32_t afH[2][4], afM[2][4];
#pragma unroll
                for (int i = 0; i < 2; ++i) {
                    ldm_x4(AH + aoff + i * (16 * SP * 2),
                           afH[i][0], afH[i][1], afH[i][2], afH[i][3]);
                    ldm_x4(AM + aoff + i * (16 * SP * 2),
                           afM[i][0], afM[i][1], afM[i][2], afM[i][3]);
                }
                uint32_t bfH[4][2], bfM[4][2];
#pragma unroll
                for (int jp = 0; jp < 2; ++jp) {
                    ldm_x4(BH + boff + jp * (16 * SP * 2),
                           bfH[2*jp][0], bfH[2*jp][1], bfH[2*jp+1][0], bfH[2*jp+1][1]);
                    ldm_x4(BM + boff + jp * (16 * SP * 2),
                           bfM[2*jp][0], bfM[2*jp][1], bfM[2*jp+1][0], bfM[2*jp+1][1]);
                }
#pragma unroll
                for (int i = 0; i < 2; ++i)
#pragma unroll
                    for (int j = 0; j < 4; ++j) {
                        mma16816(acc[i][j], afH[i], bfH[j]);   // hh
                        mma16816(acc[i][j], afH[i], bfM[j]);   // hm
                        mma16816(acc[i][j], afM[i], bfH[j]);   // mh
                    }
            }
        }

        // ============ Phase C: epilogue1 ============
        {
            float p3[2][2] = {{0.f, 0.f}, {0.f, 0.f}};
#pragma unroll
            for (int i = 0; i < 2; ++i) {
                const int m0 = wm * 32 + i * 16 + q;
#pragma unroll
                for (int j = 0; j < 4; ++j) {
                    const int n0 = wn * 32 + j * 8 + cb;
                    float h0 = fmaxf(acc[i][j][0] + b1f[n0],     0.f);
                    float h1 = fmaxf(acc[i][j][1] + b1f[n0 + 1], 0.f);
                    float h2 = fmaxf(acc[i][j][2] + b1f[n0],     0.f);
                    float h3 = fmaxf(acc[i][j][3] + b1f[n0 + 1], 0.f);
                    p3[i][0] += h0 * w2r3[n0] + h1 * w2r3[n0 + 1];
                    p3[i][1] += h2 * w2r3[n0] + h3 * w2r3[n0 + 1];
                    *(uint32_t*)(smem + OFF_H + (m0 * SH + n0) * 2)       = pack2(h0, h1);
                    *(uint32_t*)(smem + OFF_H + ((m0 + 8) * SH + n0) * 2) = pack2(h2, h3);
                }
            }
#pragma unroll
            for (int i = 0; i < 2; ++i)
#pragma unroll
                for (int r = 0; r < 2; ++r) {
                    float v = p3[i][r];
                    v += __shfl_xor_sync(0xFFFFFFFF, v, 1);
                    v += __shfl_xor_sync(0xFFFFFFFF, v, 2);
                    if ((l & 3) == 0)
                        atomicAdd(&sC3[wm * 32 + i * 16 + q + r * 8], v);
                }
        }
        __syncthreads();

        // ch3 finalize
        if (tid < TM) {
            const int m = tid, px = xb + m;
            const uint32_t pix = ((uint32_t)b << 16) + ((uint32_t)y << 8) + px;
            const float fire = (ru[pix] <= 0.5f) ? 1.f : 0.f;
            const uint32_t i3 = (((uint32_t)b * CHN + 3) << 16) + ((uint32_t)y << 8) + px;
            g_x2[i3] = sXC[m * 33 + 3] + sC3[m] * fire;
            sC3[m] = 0.f;
        }

        // ============ Phase D: GEMM2 (M64 x N32 x K256), 16 warps = 2M x 4N x 2K ============
        {
            const int wm2 = wid & 1, wn2 = (wid >> 1) & 3, wk2 = wid >> 3;
            float ac2[2][4];
#pragma unroll
            for (int i = 0; i < 2; ++i)
#pragma unroll
                for (int e = 0; e < 4; ++e) ac2[i][e] = 0.f;
            const uint32_t Hb = sbase + OFF_H, W2b = sbase + OFF_W2H;
#pragma unroll
            for (int ks = 0; ks < 8; ++ks) {
                const int k0 = wk2 * 128 + ks * 16;
                uint32_t af[2][4];
#pragma unroll
                for (int i = 0; i < 2; ++i) {
                    uint32_t row = wm2 * 32 + i * 16 + (l & 15);
                    ldm_x4(Hb + (row * SH + k0 + ((l >> 4) << 3)) * 2,
                           af[i][0], af[i][1], af[i][2], af[i][3]);
                }
                uint32_t bf[2];
                {
                    uint32_t rn = wn2 * 8 + (l & 7);
                    ldm_x2(W2b + (rn * SH + k0 + (((l >> 3) & 1) << 3)) * 2, bf[0], bf[1]);
                }
#pragma unroll
                for (int i = 0; i < 2; ++i) mma16816(ac2[i], af[i], bf);
            }
            __syncthreads();   // sPart aliases sP region
#pragma unroll
            for (int i = 0; i < 2; ++i)
#pragma unroll
                for (int e = 0; e < 4; ++e) {
                    const int m = wm2 * 32 + i * 16 + q + (e >> 1) * 8;
                    const int n = wn2 * 8 + cb + (e & 1);
                    sPart[(wk2 * TM + m) * 32 + n] = ac2[i][e];
                }
        }
        __syncthreads();

        // ============ Phase E: writeback (8 groups x 4 channels) ============
        {
            const int m = tid & 63, ng = tid >> 6;
            const int px = xb + m;
            const uint32_t pix = ((uint32_t)b << 16) + ((uint32_t)y << 8) + px;
            const float fire = (ru[pix] <= 0.5f) ? 1.f : 0.f;
#pragma unroll
            for (int q2 = 0; q2 < 4; ++q2) {
                const int ch = ng * 4 + q2;
                if (ch == 3) continue;
                const float upd = sPart[m * 32 + ch] + sPart[(TM + m) * 32 + ch];
                const uint32_t idx = (((uint32_t)b * CHN + ch) << 16) + ((uint32_t)y << 8) + px;
                g_x2[idx] = sXC[m * 33 + ch] + upd * fire;
            }
        }
        __syncthreads();
    }
}

// ---------------------------------------------------------------------------
__global__ __launch_bounds__(256)
void nca_mask_kernel(const float* __restrict__ x, float* __restrict__ out)
{
    int gid = blockIdx.x * 256 + threadIdx.x;
    int b  = gid >> 16;
    int y  = (gid >> 8) & 255;
    int xx = gid & 255;

    const float* xc  = x    + (((uint32_t)b * CHN + 3) << 16);
    const float* x2c = g_x2 + (((uint32_t)b * CHN + 3) << 16);

    float m1 = -1e30f, m2 = -1e30f;
    int y0 = y > 0 ? y - 1 : 0, y1 = y < HW - 1 ? y + 1 : HW - 1;
    int x0 = xx > 0 ? xx - 1 : 0, x1 = xx < HW - 1 ? xx + 1 : HW - 1;
    for (int yy = y0; yy <= y1; ++yy)
        for (int xw = x0; xw <= x1; ++xw) {
            m1 = fmaxf(m1, xc[yy * HW + xw]);
            m2 = fmaxf(m2, x2c[yy * HW + xw]);
        }
    float life = (m1 > 0.1f && m2 > 0.1f) ? 1.f : 0.f;

    uint32_t base = ((uint32_t)b * CHN << 16) + ((uint32_t)y << 8) + xx;
#pragma unroll
    for (int o = 0; o < CHN; ++o)
        out[base + ((uint32_t)o << 16)] = g_x2[base + ((uint32_t)o << 16)] * life;
}

// ---------------------------------------------------------------------------
extern "C" void kernel_launch(void* const* d_in, const int* in_sizes, int n_in,
                              void* d_out, int out_size)
{
    const float* x  = (const float*)d_in[0];
    const float* ru = (const float*)d_in[1];
    const float* W1 = (const float*)d_in[2];
    const float* b1 = (const float*)d_in[3];
    const float* W2 = (const float*)d_in[4];
    float* out = (float*)d_out;

    cudaFuncSetAttribute(nca_mma_kernel,
                         cudaFuncAttributeMaxDynamicSharedMemorySize, SMEM_TOTAL);
    nca_mma_kernel<<<NCTAS, NTH, SMEM_TOTAL>>>(x, ru, W1, b1, W2);
    nca_mask_kernel<<<(8 * HW * HW) / 256, 256>>>(x, out);
}

// round 10
// speedup vs baseline: 1.1058x; 1.1058x over previous
#include <cuda_runtime.h>
#include <cuda_bf16.h>
#include <cstdint>

#define HW 256
#define CHN 32
#define HID 256
#define K1 96
#define SP 104          // row stride (bf16 elems) for P / W1
#define SH 264          // row stride (bf16 elems) for H / W2
#define TM 64           // pixels per tile
#define NTILES 8192
#define NCTAS 148

// smem byte offsets
#define OFF_W1H 0
#define OFF_W1M (OFF_W1H + HID*SP*2)
#define OFF_W2H (OFF_W1M + HID*SP*2)
#define OFF_B1  (OFF_W2H + CHN*SH*2)
#define OFF_W2R3 (OFF_B1 + HID*4)
#define OFF_PH  (OFF_W2R3 + HID*4)
#define OFF_PM  (OFF_PH + TM*SP*2)
#define OFF_H   (OFF_PM + TM*SP*2)
#define OFF_PART OFF_PH                        // 16KB, aliases dead P region
#define OFF_RB  (OFF_H + TM*SH*2 + 16)        // 185872 (16B aligned)
#define RB_CH   220
#define RB_ROW  72
#define OFF_XC  (OFF_RB + CHN*RB_CH*4)        // 214032
#define OFF_RU  (OFF_XC + TM*33*4)            // 222480 (16B aligned)
#define OFF_C3P (OFF_RU + TM*4)               // 222736
#define SMEM_TOTAL (OFF_C3P + 4*TM*4)         // 223760

__device__ float g_x2[8 * CHN * HW * HW];

__device__ __forceinline__ uint32_t smem_u32(const void* p) {
    uint32_t a;
    asm("{ .reg .u64 t; cvta.to.shared.u64 t, %1; cvt.u32.u64 %0, t; }" : "=r"(a) : "l"(p));
    return a;
}
__device__ __forceinline__ void ldm_x4(uint32_t a, uint32_t& r0, uint32_t& r1, uint32_t& r2, uint32_t& r3) {
    asm volatile("ldmatrix.sync.aligned.m8n8.x4.shared.b16 {%0,%1,%2,%3}, [%4];"
                 : "=r"(r0), "=r"(r1), "=r"(r2), "=r"(r3) : "r"(a));
}
__device__ __forceinline__ void ldm_x2(uint32_t a, uint32_t& r0, uint32_t& r1) {
    asm volatile("ldmatrix.sync.aligned.m8n8.x2.shared.b16 {%0,%1}, [%2];"
                 : "=r"(r0), "=r"(r1) : "r"(a));
}
__device__ __forceinline__ void mma16816(float* d, const uint32_t* a, const uint32_t* b) {
    asm volatile("mma.sync.aligned.m16n8k16.row.col.f32.bf16.bf16.f32 "
                 "{%0,%1,%2,%3}, {%4,%5,%6,%7}, {%8,%9}, {%0,%1,%2,%3};"
                 : "+f"(d[0]), "+f"(d[1]), "+f"(d[2]), "+f"(d[3])
                 : "r"(a[0]), "r"(a[1]), "r"(a[2]), "r"(a[3]), "r"(b[0]), "r"(b[1]));
}
__device__ __forceinline__ uint32_t pack2(float lo, float hi) {
    __nv_bfloat162 t = __floats2bfloat162_rn(lo, hi);
    return *(uint32_t*)&t;
}
__device__ __forceinline__ uint32_t pkraw(__nv_bfloat16 lo, __nv_bfloat16 hi) {
    return ((uint32_t)__bfloat16_as_ushort(hi) << 16) | (uint32_t)__bfloat16_as_ushort(lo);
}

// ---------------------------------------------------------------------------
__global__ __launch_bounds__(256, 1)
void nca_mma_kernel(const float* __restrict__ x, const float* __restrict__ ru,
                    const float* __restrict__ W1, const float* __restrict__ b1,
                    const float* __restrict__ W2)
{
    extern __shared__ char smem[];
    const uint32_t sbase = smem_u32(smem);
    const int tid = threadIdx.x;
    const int wid = tid >> 5;
    const int l   = tid & 31;

    // ---- one-time: weights into smem
    for (int idx = tid; idx < HID * K1; idx += 256) {
        int n = idx / K1, k = idx - n * K1;
        float v = W1[idx];
        __nv_bfloat16 h = __float2bfloat16_rn(v);
        float r = v - __bfloat162float(h);
        *(__nv_bfloat16*)(smem + OFF_W1H + (n * SP + k) * 2) = h;
        *(__nv_bfloat16*)(smem + OFF_W1M + (n * SP + k) * 2) = __float2bfloat16_rn(r);
    }
    for (int idx = tid; idx < CHN * HID; idx += 256) {
        int n = idx >> 8, k = idx & 255;
        *(__nv_bfloat16*)(smem + OFF_W2H + (n * SH + k) * 2) = __float2bfloat16_rn(W2[idx]);
    }
    for (int idx = tid; idx < HID; idx += 256) {
        ((float*)(smem + OFF_B1))[idx]   = b1[idx];
        ((float*)(smem + OFF_W2R3))[idx] = W2[3 * HID + idx];
    }
    __syncthreads();

    const float* b1f   = (const float*)(smem + OFF_B1);
    const float* w2r3  = (const float*)(smem + OFF_W2R3);
    float*       sC3P  = (float*)(smem + OFF_C3P);   // [4][64] per-wn partials
    float*       sPart = (float*)(smem + OFF_PART);
    const float* rb    = (const float*)(smem + OFF_RB);
    float*       sXC   = (float*)(smem + OFF_XC);
    const float* sRU   = (const float*)(smem + OFF_RU);

    const int q  = l >> 2;
    const int cb = 2 * (l & 3);

    // ---- tile-invariant prefetch chunk geometry (x: 1728 chunks, ru: 16 chunks) ----
    int pfRow[7], pfCx[7];
    uint32_t pfDst[7], pfChO[7];
    int nPf = 0;
    for (int k = 0; k < 7; ++k) {
        int i = tid + 256 * k;
        if (i < 1728) {
            int ch  = i / 54;
            int rem = i - ch * 54;
            int row = rem / 18;
            int cx  = rem - row * 18;
            pfRow[nPf] = row;
            pfCx[nPf]  = cx;
            pfChO[nPf] = ((uint32_t)ch << 16);
            pfDst[nPf] = sbase + OFF_RB + (uint32_t)(ch * RB_CH + row * RB_ROW + cx * 4) * 4;
            ++nPf;
        } else if (i < 1744) {
            int cx = i - 1728;                 // 0..15, 16B each
            pfRow[nPf] = 3;                    // sentinel: ru chunk
            pfCx[nPf]  = cx;
            pfChO[nPf] = 0;
            pfDst[nPf] = sbase + OFF_RU + (uint32_t)cx * 16;
            ++nPf;
        }
    }

    auto prefetch = [&](int tile) {
        const int b  = tile >> 10;
        const int rr = tile & 1023;
        const int y  = rr >> 2;
        const int xb = (rr & 3) << 6;
        const float* xim = x + (uint32_t)b * (CHN * HW * HW);
        const float* rurow = ru + (((uint32_t)b << 16) + ((uint32_t)y << 8) + xb);
        for (int k = 0; k < nPf; ++k) {
            if (pfRow[k] == 3) {
                const float* src = rurow + pfCx[k] * 4;
                asm volatile("cp.async.ca.shared.global [%0], [%1], 16, 16;"
                             :: "r"(pfDst[k]), "l"(src));
            } else {
                const int srow = y - 1 + pfRow[k];
                const int px0  = xb - 4 + pfCx[k] * 4;
                const bool ok = (srow >= 0) & (srow < HW) & (px0 >= 0) & (px0 <= HW - 4);
                const float* src = xim + pfChO[k] + ((uint32_t)(srow & 255) << 8) + (px0 & 255);
                const int sz = ok ? 16 : 0;
                asm volatile("cp.async.ca.shared.global [%0], [%1], 16, %2;"
                             :: "r"(pfDst[k]), "l"(src), "r"(sz));
            }
        }
        asm volatile("cp.async.commit_group;" ::: "memory");
    };

    if (blockIdx.x < NTILES) prefetch(blockIdx.x);

    for (int tile = blockIdx.x; tile < NTILES; tile += NCTAS) {
        const int b  = tile >> 10;
        const int rr = tile & 1023;
        const int y  = rr >> 2;
        const int xb = (rr & 3) << 6;

        asm volatile("cp.async.wait_group 0;" ::: "memory");
        __syncthreads();                                    // B1

        // grab this tile's ru before next prefetch can overwrite the slot
        const float myRu = sRU[tid & 63];
        const float fire = (myRu <= 0.5f) ? 1.f : 0.f;

        // ============ Phase A: perceive from RB, packed-pair split stores ============
        {
            const int c0 = wid * 4;
            uint32_t* pH = (uint32_t*)(smem + OFF_PH);
            uint32_t* pM = (uint32_t*)(smem + OFF_PM);
#pragma unroll
            for (int half = 0; half < 2; ++half) {
                const int pp = l + 32 * half;
                const int wbase = pp * 52 + 6 * wid;
#pragma unroll
                for (int cp = 0; cp < 2; ++cp) {
                    float vv[6];
#pragma unroll
                    for (int u = 0; u < 2; ++u) {
                        const int c = c0 + 2 * cp + u;
                        const float* r0 = rb + c * RB_CH + (pp + 3);
                        const float* r1 = r0 + RB_ROW;
                        const float* r2 = r1 + RB_ROW;
                        float a00 = r0[0], a01 = r0[1], a02 = r0[2];
                        float a10 = r1[0], a11 = r1[1], a12 = r1[2];
                        float a20 = r2[0], a21 = r2[1], a22 = r2[2];
                        vv[3 * u]     = a11;
                        vv[3 * u + 1] = ((a02 - a00) + 2.f * (a12 - a10) + (a22 - a20)) * 0.125f;
                        vv[3 * u + 2] = ((a20 - a00) + 2.f * (a21 - a01) + (a22 - a02)) * 0.125f;
                        sXC[pp * 33 + c] = a11;
                    }
                    __nv_bfloat16 h[6];
                    uint32_t mw[3];
#pragma unroll
                    for (int j = 0; j < 3; ++j) {
                        h[2*j]   = __float2bfloat16_rn(vv[2*j]);
                        h[2*j+1] = __float2bfloat16_rn(vv[2*j+1]);
                        __nv_bfloat16 m0 = __float2bfloat16_rn(vv[2*j]   - __bfloat162float(h[2*j]));
                        __nv_bfloat16 m1 = __float2bfloat16_rn(vv[2*j+1] - __bfloat162float(h[2*j+1]));
                        mw[j] = pkraw(m0, m1);
                    }
                    const int wofs = wbase + 3 * cp;
                    pH[wofs]     = pkraw(h[0], h[1]);
                    pH[wofs + 1] = pkraw(h[2], h[3]);
                    pH[wofs + 2] = pkraw(h[4], h[5]);
                    pM[wofs]     = mw[0];
                    pM[wofs + 1] = mw[1];
                    pM[wofs + 2] = mw[2];
                }
            }
        }
        __syncthreads();                                    // B2

        if (tile + NCTAS < NTILES) prefetch(tile + NCTAS);

        // ============ Phase B: GEMM1 (M64 x N256 x K96), fragment-reuse, 3 products ============
        const int wm = wid >> 2, wn = wid & 3;
        float acc[2][8][4];
#pragma unroll
        for (int i = 0; i < 2; ++i)
#pragma unroll
            for (int j = 0; j < 8; ++j)
#pragma unroll
                for (int e = 0; e < 4; ++e) acc[i][j][e] = 0.f;
        {
            const int gi = l >> 3;
            const int gj = (gi >> 1) * 8 + (l & 7);
            const int gk = (gi & 1) << 3;
            const uint32_t AH = sbase + OFF_PH, AM = sbase + OFF_PM;
            const uint32_t BH = sbase + OFF_W1H, BM = sbase + OFF_W1M;
#pragma unroll
            for (int ks = 0; ks < 6; ++ks) {
                const int k0 = ks * 16;
                const uint32_t aoff = ((wm * 32 + (l & 15)) * SP + k0 + ((l >> 4) << 3)) * 2;
                const uint32_t boff = ((wn * 64 + gj) * SP + k0 + gk) * 2;
                uint32_t afH[2][4], afM[2][4];
#pragma unroll
                for (int i = 0; i < 2; ++i) {
                    ldm_x4(AH + aoff + i * (16 * SP * 2),
                           afH[i][0], afH[i][1], afH[i][2], afH[i][3]);
                    ldm_x4(AM + aoff + i * (16 * SP * 2),
                           afM[i][0], afM[i][1], afM[i][2], afM[i][3]);
                }
                uint32_t bfH[8][2], bfM[8][2];
#pragma unroll
                for (int jp = 0; jp < 4; ++jp) {
                    ldm_x4(BH + boff + jp * (16 * SP * 2),
                           bfH[2*jp][0], bfH[2*jp][1], bfH[2*jp+1][0], bfH[2*jp+1][1]);
                    ldm_x4(BM + boff + jp * (16 * SP * 2),
                           bfM[2*jp][0], bfM[2*jp][1], bfM[2*jp+1][0], bfM[2*jp+1][1]);
                }
#pragma unroll
                for (int i = 0; i < 2; ++i)
#pragma unroll
                    for (int j = 0; j < 8; ++j) {
                        mma16816(acc[i][j], afH[i], bfH[j]);   // hh
                        mma16816(acc[i][j], afH[i], bfM[j]);   // hm
                        mma16816(acc[i][j], afM[i], bfH[j]);   // mh
                    }
            }
        }

        // ============ Phase C: epilogue1 — bias+relu, pack H, ch3 partials (no atomics) ============
        {
            float p3[2][2] = {{0.f, 0.f}, {0.f, 0.f}};
#pragma unroll
            for (int i = 0; i < 2; ++i) {
                const int m0 = wm * 32 + i * 16 + q;
#pragma unroll
                for (int j = 0; j < 8; ++j) {
                    const int n0 = wn * 64 + j * 8 + cb;
                    float h0 = fmaxf(acc[i][j][0] + b1f[n0],     0.f);
                    float h1 = fmaxf(acc[i][j][1] + b1f[n0 + 1], 0.f);
                    float h2 = fmaxf(acc[i][j][2] + b1f[n0],     0.f);
                    float h3 = fmaxf(acc[i][j][3] + b1f[n0 + 1], 0.f);
                    p3[i][0] += h0 * w2r3[n0] + h1 * w2r3[n0 + 1];
                    p3[i][1] += h2 * w2r3[n0] + h3 * w2r3[n0 + 1];
                    *(uint32_t*)(smem + OFF_H + (m0 * SH + n0) * 2)       = pack2(h0, h1);
                    *(uint32_t*)(smem + OFF_H + ((m0 + 8) * SH + n0) * 2) = pack2(h2, h3);
                }
            }
#pragma unroll
            for (int i = 0; i < 2; ++i)
#pragma unroll
                for (int r = 0; r < 2; ++r) {
                    float v = p3[i][r];
                    v += __shfl_xor_sync(0xFFFFFFFF, v, 1);
                    v += __shfl_xor_sync(0xFFFFFFFF, v, 2);
                    if ((l & 3) == 0)
                        sC3P[wn * TM + wm * 32 + i * 16 + q + r * 8] = v;
                }
        }
        __syncthreads();                                    // B3

        // ch3 finalize: exact x2[ch3] from sXC + summed partials (ru from smem)
        if (tid < TM) {
            const int m = tid, px = xb + m;
            const float p3sum = sC3P[m] + sC3P[TM + m] + sC3P[2 * TM + m] + sC3P[3 * TM + m];
            const uint32_t i3 = (((uint32_t)b * CHN + 3) << 16) + ((uint32_t)y << 8) + px;
            g_x2[i3] = sXC[m * 33 + 3] + p3sum * fire;
        }

        // ============ Phase D: GEMM2 (M64 x N32 x K256, hi only) ============
        {
            const int wm2 = wid & 1, wn2 = (wid >> 1) & 1, wk2 = wid >> 2;
            float ac2[2][2][4];
#pragma unroll
            for (int i = 0; i < 2; ++i)
#pragma unroll
                for (int j = 0; j < 2; ++j)
#pragma unroll
                    for (int e = 0; e < 4; ++e) ac2[i][j][e] = 0.f;
            const uint32_t Hb = sbase + OFF_H, W2b = sbase + OFF_W2H;
#pragma unroll
            for (int ks = 0; ks < 8; ++ks) {
                const int k0 = wk2 * 128 + ks * 16;
                uint32_t af[2][4];
#pragma unroll
                for (int i = 0; i < 2; ++i) {
                    uint32_t row = wm2 * 32 + i * 16 + (l & 15);
                    ldm_x4(Hb + (row * SH + k0 + ((l >> 4) << 3)) * 2,
                           af[i][0], af[i][1], af[i][2], af[i][3]);
                }
                uint32_t bf[2][2];
#pragma unroll
                for (int j = 0; j < 2; ++j) {
                    uint32_t rn = wn2 * 16 + j * 8 + (l & 7);
                    ldm_x2(W2b + (rn * SH + k0 + (((l >> 3) & 1) << 3)) * 2,
                           bf[j][0], bf[j][1]);
                }
#pragma unroll
                for (int i = 0; i < 2; ++i)
#pragma unroll
                    for (int j = 0; j < 2; ++j) mma16816(ac2[i][j], af[i], bf[j]);
            }
            // sPart aliases P region; last P reads were GEMM1 (pre-B3) -> safe, no barrier
#pragma unroll
            for (int i = 0; i < 2; ++i)
#pragma unroll
                for (int j = 0; j < 2; ++j)
#pragma unroll
                    for (int e = 0; e < 4; ++e) {
                        const int m = wm2 * 32 + i * 16 + q + (e >> 1) * 8;
                        const int n = wn2 * 16 + j * 8 + cb + (e & 1);
                        sPart[(wk2 * TM + m) * 32 + n] = ac2[i][j][e];
                    }
        }
        __syncthreads();                                    // B4

        // ============ Phase E: writeback from sXC (skip ch3), ru from register ============
        {
            const int m = tid & 63, ng = tid >> 6;
            const int px = xb + m;
#pragma unroll
            for (int q2 = 0; q2 < 8; ++q2) {
                const int ch = ng * 8 + q2;
                if (ch == 3) continue;
                const float upd = sPart[m * 32 + ch] + sPart[(TM + m) * 32 + ch];
                const uint32_t idx = (((uint32_t)b * CHN + ch) << 16) + ((uint32_t)y << 8) + px;
                g_x2[idx] = sXC[m * 33 + ch] + upd * fire;
            }
        }
        __syncthreads();                                    // B5
    }
}

// ---------------------------------------------------------------------------
__global__ __launch_bounds__(256)
void nca_mask_kernel(const float* __restrict__ x, float* __restrict__ out)
{
    int gid = blockIdx.x * 256 + threadIdx.x;
    int b  = gid >> 16;
    int y  = (gid >> 8) & 255;
    int xx = gid & 255;

    const float* xc  = x    + (((uint32_t)b * CHN + 3) << 16);
    const float* x2c = g_x2 + (((uint32_t)b * CHN + 3) << 16);

    float m1 = -1e30f, m2 = -1e30f;
    int y0 = y > 0 ? y - 1 : 0, y1 = y < HW - 1 ? y + 1 : HW - 1;
    int x0 = xx > 0 ? xx - 1 : 0, x1 = xx < HW - 1 ? xx + 1 : HW - 1;
    for (int yy = y0; yy <= y1; ++yy)
        for (int xw = x0; xw <= x1; ++xw) {
            m1 = fmaxf(m1, xc[yy * HW + xw]);
            m2 = fmaxf(m2, x2c[yy * HW + xw]);
        }
    float life = (m1 > 0.1f && m2 > 0.1f) ? 1.f : 0.f;

    uint32_t base = ((uint32_t)b * CHN << 16) + ((uint32_t)y << 8) + xx;
#pragma unroll
    for (int o = 0; o < CHN; ++o)
        out[base + ((uint32_t)o << 16)] = g_x2[base + ((uint32_t)o << 16)] * life;
}

// ---------------------------------------------------------------------------
extern "C" void kernel_launch(void* const* d_in, const int* in_sizes, int n_in,
                              void* d_out, int out_size)
{
    const float* x  = (const float*)d_in[0];
    const float* ru = (const float*)d_in[1];
    const float* W1 = (const float*)d_in[2];
    const float* b1 = (const float*)d_in[3];
    const float* W2 = (const float*)d_in[4];
    float* out = (float*)d_out;

    cudaFuncSetAttribute(nca_mma_kernel,
                         cudaFuncAttributeMaxDynamicSharedMemorySize, SMEM_TOTAL);
    nca_mma_kernel<<<NCTAS, 256, SMEM_TOTAL>>>(x, ru, W1, b1, W2);
    nca_mask_kernel<<<(8 * HW * HW) / 256, 256>>>(x, out);
}

// round 11
// speedup vs baseline: 1.1792x; 1.0664x over previous
#include <cuda_runtime.h>
#include <cuda_bf16.h>
#include <cstdint>

#define HW 256
#define CHN 32
#define HID 256
#define K1 96
#define SP 104          // row stride (bf16 elems) for P / W1
#define SH 264          // row stride (bf16 elems) for H / W2
#define TM 64           // pixels per tile
#define NTILES 8192
#define NCTAS 148

// smem byte offsets
#define OFF_W1H 0
#define OFF_W1M (OFF_W1H + HID*SP*2)
#define OFF_W2H (OFF_W1M + HID*SP*2)
#define OFF_B1  (OFF_W2H + CHN*SH*2)
#define OFF_W2R3 (OFF_B1 + HID*4)
#define OFF_PH  (OFF_W2R3 + HID*4)
#define OFF_PM  (OFF_PH + TM*SP*2)
#define OFF_H   (OFF_PM + TM*SP*2)
#define OFF_RB  (OFF_H + TM*SH*2 + 16)        // 185872 (16B aligned)
#define RB_CH   220
#define RB_ROW  72
#define OFF_XC  (OFF_RB + CHN*RB_CH*4)        // 214032
#define OFF_RU  (OFF_XC + TM*33*4)            // 222480 (16B aligned)
#define OFF_C3P (OFF_RU + TM*4)               // 222736
#define OFF_FIRE (OFF_C3P + 4*TM*4)           // 223760
#define SMEM_TOTAL (OFF_FIRE + TM*4)          // 224016

__device__ float g_x2[8 * CHN * HW * HW];

__device__ __forceinline__ uint32_t smem_u32(const void* p) {
    uint32_t a;
    asm("{ .reg .u64 t; cvta.to.shared.u64 t, %1; cvt.u32.u64 %0, t; }" : "=r"(a) : "l"(p));
    return a;
}
__device__ __forceinline__ void ldm_x4(uint32_t a, uint32_t& r0, uint32_t& r1, uint32_t& r2, uint32_t& r3) {
    asm volatile("ldmatrix.sync.aligned.m8n8.x4.shared.b16 {%0,%1,%2,%3}, [%4];"
                 : "=r"(r0), "=r"(r1), "=r"(r2), "=r"(r3) : "r"(a));
}
__device__ __forceinline__ void ldm_x2(uint32_t a, uint32_t& r0, uint32_t& r1) {
    asm volatile("ldmatrix.sync.aligned.m8n8.x2.shared.b16 {%0,%1}, [%2];"
                 : "=r"(r0), "=r"(r1) : "r"(a));
}
__device__ __forceinline__ void mma16816(float* d, const uint32_t* a, const uint32_t* b) {
    asm volatile("mma.sync.aligned.m16n8k16.row.col.f32.bf16.bf16.f32 "
                 "{%0,%1,%2,%3}, {%4,%5,%6,%7}, {%8,%9}, {%0,%1,%2,%3};"
                 : "+f"(d[0]), "+f"(d[1]), "+f"(d[2]), "+f"(d[3])
                 : "r"(a[0]), "r"(a[1]), "r"(a[2]), "r"(a[3]), "r"(b[0]), "r"(b[1]));
}
__device__ __forceinline__ uint32_t pack2(float lo, float hi) {
    __nv_bfloat162 t = __floats2bfloat162_rn(lo, hi);
    return *(uint32_t*)&t;
}
__device__ __forceinline__ uint32_t pkraw(__nv_bfloat16 lo, __nv_bfloat16 hi) {
    return ((uint32_t)__bfloat16_as_ushort(hi) << 16) | (uint32_t)__bfloat16_as_ushort(lo);
}

// ---------------------------------------------------------------------------
__global__ __launch_bounds__(256, 1)
void nca_mma_kernel(const float* __restrict__ x, const float* __restrict__ ru,
                    const float* __restrict__ W1, const float* __restrict__ b1,
                    const float* __restrict__ W2)
{
    extern __shared__ char smem[];
    const uint32_t sbase = smem_u32(smem);
    const int tid = threadIdx.x;
    const int wid = tid >> 5;
    const int l   = tid & 31;

    // ---- one-time: weights into smem
    for (int idx = tid; idx < HID * K1; idx += 256) {
        int n = idx / K1, k = idx - n * K1;
        float v = W1[idx];
        __nv_bfloat16 h = __float2bfloat16_rn(v);
        float r = v - __bfloat162float(h);
        *(__nv_bfloat16*)(smem + OFF_W1H + (n * SP + k) * 2) = h;
        *(__nv_bfloat16*)(smem + OFF_W1M + (n * SP + k) * 2) = __float2bfloat16_rn(r);
    }
    for (int idx = tid; idx < CHN * HID; idx += 256) {
        int n = idx >> 8, k = idx & 255;
        *(__nv_bfloat16*)(smem + OFF_W2H + (n * SH + k) * 2) = __float2bfloat16_rn(W2[idx]);
    }
    for (int idx = tid; idx < HID; idx += 256) {
        ((float*)(smem + OFF_B1))[idx]   = b1[idx];
        ((float*)(smem + OFF_W2R3))[idx] = W2[3 * HID + idx];
    }
    __syncthreads();

    const float* b1f   = (const float*)(smem + OFF_B1);
    const float* w2r3  = (const float*)(smem + OFF_W2R3);
    float*       sC3P  = (float*)(smem + OFF_C3P);   // [4][64] per-wn partials
    const float* rb    = (const float*)(smem + OFF_RB);
    float*       sXC   = (float*)(smem + OFF_XC);
    const float* sRU   = (const float*)(smem + OFF_RU);
    float*       sFire = (float*)(smem + OFF_FIRE);

    const int q  = l >> 2;
    const int cb = 2 * (l & 3);

    // ---- tile-invariant prefetch chunk geometry (x: 1728 chunks, ru: 16 chunks) ----
    int pfRow[7], pfCx[7];
    uint32_t pfDst[7], pfChO[7];
    int nPf = 0;
    for (int k = 0; k < 7; ++k) {
        int i = tid + 256 * k;
        if (i < 1728) {
            int ch  = i / 54;
            int rem = i - ch * 54;
            int row = rem / 18;
            int cx  = rem - row * 18;
            pfRow[nPf] = row;
            pfCx[nPf]  = cx;
            pfChO[nPf] = ((uint32_t)ch << 16);
            pfDst[nPf] = sbase + OFF_RB + (uint32_t)(ch * RB_CH + row * RB_ROW + cx * 4) * 4;
            ++nPf;
        } else if (i < 1744) {
            int cx = i - 1728;
            pfRow[nPf] = 3;                    // sentinel: ru chunk
            pfCx[nPf]  = cx;
            pfChO[nPf] = 0;
            pfDst[nPf] = sbase + OFF_RU + (uint32_t)cx * 16;
            ++nPf;
        }
    }

    auto prefetch = [&](int tile) {
        const int b  = tile >> 10;
        const int rr = tile & 1023;
        const int y  = rr >> 2;
        const int xb = (rr & 3) << 6;
        const float* xim = x + (uint32_t)b * (CHN * HW * HW);
        const float* rurow = ru + (((uint32_t)b << 16) + ((uint32_t)y << 8) + xb);
        for (int k = 0; k < nPf; ++k) {
            if (pfRow[k] == 3) {
                const float* src = rurow + pfCx[k] * 4;
                asm volatile("cp.async.ca.shared.global [%0], [%1], 16, 16;"
                             :: "r"(pfDst[k]), "l"(src));
            } else {
                const int srow = y - 1 + pfRow[k];
                const int px0  = xb - 4 + pfCx[k] * 4;
                const bool ok = (srow >= 0) & (srow < HW) & (px0 >= 0) & (px0 <= HW - 4);
                const float* src = xim + pfChO[k] + ((uint32_t)(srow & 255) << 8) + (px0 & 255);
                const int sz = ok ? 16 : 0;
                asm volatile("cp.async.ca.shared.global [%0], [%1], 16, %2;"
                             :: "r"(pfDst[k]), "l"(src), "r"(sz));
            }
        }
        asm volatile("cp.async.commit_group;" ::: "memory");
    };

    if (blockIdx.x < NTILES) prefetch(blockIdx.x);

    for (int tile = blockIdx.x; tile < NTILES; tile += NCTAS) {
        const int b  = tile >> 10;
        const int rr = tile & 1023;
        const int y  = rr >> 2;
        const int xb = (rr & 3) << 6;

        asm volatile("cp.async.wait_group 0;" ::: "memory");
        __syncthreads();                                    // B1

        // grab this tile's ru before prefetch (at B2) can overwrite the slot;
        // stash fire in sFire for the post-B3 register writeback
        const float myRu = sRU[tid & 63];
        const float fire = (myRu <= 0.5f) ? 1.f : 0.f;
        if (tid < TM) sFire[tid] = fire;

        // ============ Phase A: perceive from RB, packed-pair split stores ============
        {
            const int c0 = wid * 4;
            uint32_t* pH = (uint32_t*)(smem + OFF_PH);
            uint32_t* pM = (uint32_t*)(smem + OFF_PM);
#pragma unroll
            for (int half = 0; half < 2; ++half) {
                const int pp = l + 32 * half;
                const int wbase = pp * 52 + 6 * wid;
#pragma unroll
                for (int cp = 0; cp < 2; ++cp) {
                    float vv[6];
#pragma unroll
                    for (int u = 0; u < 2; ++u) {
                        const int c = c0 + 2 * cp + u;
                        const float* r0 = rb + c * RB_CH + (pp + 3);
                        const float* r1 = r0 + RB_ROW;
                        const float* r2 = r1 + RB_ROW;
                        float a00 = r0[0], a01 = r0[1], a02 = r0[2];
                        float a10 = r1[0], a11 = r1[1], a12 = r1[2];
                        float a20 = r2[0], a21 = r2[1], a22 = r2[2];
                        vv[3 * u]     = a11;
                        vv[3 * u + 1] = ((a02 - a00) + 2.f * (a12 - a10) + (a22 - a20)) * 0.125f;
                        vv[3 * u + 2] = ((a20 - a00) + 2.f * (a21 - a01) + (a22 - a02)) * 0.125f;
                        sXC[pp * 33 + c] = a11;
                    }
                    __nv_bfloat16 h[6];
                    uint32_t mw[3];
#pragma unroll
                    for (int j = 0; j < 3; ++j) {
                        h[2*j]   = __float2bfloat16_rn(vv[2*j]);
                        h[2*j+1] = __float2bfloat16_rn(vv[2*j+1]);
                        __nv_bfloat16 m0 = __float2bfloat16_rn(vv[2*j]   - __bfloat162float(h[2*j]));
                        __nv_bfloat16 m1 = __float2bfloat16_rn(vv[2*j+1] - __bfloat162float(h[2*j+1]));
                        mw[j] = pkraw(m0, m1);
                    }
                    const int wofs = wbase + 3 * cp;
                    pH[wofs]     = pkraw(h[0], h[1]);
                    pH[wofs + 1] = pkraw(h[2], h[3]);
                    pH[wofs + 2] = pkraw(h[4], h[5]);
                    pM[wofs]     = mw[0];
                    pM[wofs + 1] = mw[1];
                    pM[wofs + 2] = mw[2];
                }
            }
        }
        __syncthreads();                                    // B2

        if (tile + NCTAS < NTILES) prefetch(tile + NCTAS);

        // ============ Phase B: GEMM1 (M64 x N256 x K96), fragment-reuse, 3 products ============
        const int wm = wid >> 2, wn = wid & 3;
        float acc[2][8][4];
#pragma unroll
        for (int i = 0; i < 2; ++i)
#pragma unroll
            for (int j = 0; j < 8; ++j)
#pragma unroll
                for (int e = 0; e < 4; ++e) acc[i][j][e] = 0.f;
        {
            const int gi = l >> 3;
            const int gj = (gi >> 1) * 8 + (l & 7);
            const int gk = (gi & 1) << 3;
            const uint32_t AH = sbase + OFF_PH, AM = sbase + OFF_PM;
            const uint32_t BH = sbase + OFF_W1H, BM = sbase + OFF_W1M;
#pragma unroll
            for (int ks = 0; ks < 6; ++ks) {
                const int k0 = ks * 16;
                const uint32_t aoff = ((wm * 32 + (l & 15)) * SP + k0 + ((l >> 4) << 3)) * 2;
                const uint32_t boff = ((wn * 64 + gj) * SP + k0 + gk) * 2;
                uint32_t afH[2][4], afM[2][4];
#pragma unroll
                for (int i = 0; i < 2; ++i) {
                    ldm_x4(AH + aoff + i * (16 * SP * 2),
                           afH[i][0], afH[i][1], afH[i][2], afH[i][3]);
                    ldm_x4(AM + aoff + i * (16 * SP * 2),
                           afM[i][0], afM[i][1], afM[i][2], afM[i][3]);
                }
                uint32_t bfH[8][2], bfM[8][2];
#pragma unroll
                for (int jp = 0; jp < 4; ++jp) {
                    ldm_x4(BH + boff + jp * (16 * SP * 2),
                           bfH[2*jp][0], bfH[2*jp][1], bfH[2*jp+1][0], bfH[2*jp+1][1]);
                    ldm_x4(BM + boff + jp * (16 * SP * 2),
                           bfM[2*jp][0], bfM[2*jp][1], bfM[2*jp+1][0], bfM[2*jp+1][1]);
                }
#pragma unroll
                for (int i = 0; i < 2; ++i)
#pragma unroll
                    for (int j = 0; j < 8; ++j) {
                        mma16816(acc[i][j], afH[i], bfH[j]);   // hh
                        mma16816(acc[i][j], afH[i], bfM[j]);   // hm
                        mma16816(acc[i][j], afM[i], bfH[j]);   // mh
                    }
            }
        }

        // ============ Phase C: epilogue1 — bias+relu, pack H, ch3 partials ============
        {
            float p3[2][2] = {{0.f, 0.f}, {0.f, 0.f}};
#pragma unroll
            for (int i = 0; i < 2; ++i) {
                const int m0 = wm * 32 + i * 16 + q;
#pragma unroll
                for (int j = 0; j < 8; ++j) {
                    const int n0 = wn * 64 + j * 8 + cb;
                    float h0 = fmaxf(acc[i][j][0] + b1f[n0],     0.f);
                    float h1 = fmaxf(acc[i][j][1] + b1f[n0 + 1], 0.f);
                    float h2 = fmaxf(acc[i][j][2] + b1f[n0],     0.f);
                    float h3 = fmaxf(acc[i][j][3] + b1f[n0 + 1], 0.f);
                    p3[i][0] += h0 * w2r3[n0] + h1 * w2r3[n0 + 1];
                    p3[i][1] += h2 * w2r3[n0] + h3 * w2r3[n0 + 1];
                    *(uint32_t*)(smem + OFF_H + (m0 * SH + n0) * 2)       = pack2(h0, h1);
                    *(uint32_t*)(smem + OFF_H + ((m0 + 8) * SH + n0) * 2) = pack2(h2, h3);
                }
            }
#pragma unroll
            for (int i = 0; i < 2; ++i)
#pragma unroll
                for (int r = 0; r < 2; ++r) {
                    float v = p3[i][r];
                    v += __shfl_xor_sync(0xFFFFFFFF, v, 1);
                    v += __shfl_xor_sync(0xFFFFFFFF, v, 2);
                    if ((l & 3) == 0)
                        sC3P[wn * TM + wm * 32 + i * 16 + q + r * 8] = v;
                }
        }
        __syncthreads();                                    // B3

        // ch3 finalize: exact x2[ch3] from sXC + summed partials
        if (tid < TM) {
            const int m = tid, px = xb + m;
            const float p3sum = sC3P[m] + sC3P[TM + m] + sC3P[2 * TM + m] + sC3P[3 * TM + m];
            const uint32_t i3 = (((uint32_t)b * CHN + 3) << 16) + ((uint32_t)y << 8) + px;
            g_x2[i3] = sXC[m * 33 + 3] + p3sum * fire;
        }

        // ============ Phase D: GEMM2 (M64 x N32 x K256, full-K per warp) +
        //              direct register writeback (no sPart, no extra barrier) ============
        {
            const int wm2 = wid & 1, wn2 = wid >> 1;        // 2M x 4N
            float ac2[2][4];
#pragma unroll
            for (int i = 0; i < 2; ++i)
#pragma unroll
                for (int e = 0; e < 4; ++e) ac2[i][e] = 0.f;
            const uint32_t Hb = sbase + OFF_H, W2b = sbase + OFF_W2H;
#pragma unroll
            for (int ks = 0; ks < 16; ++ks) {
                const int k0 = ks * 16;
                uint32_t af[2][4];
#pragma unroll
                for (int i = 0; i < 2; ++i) {
                    uint32_t row = wm2 * 32 + i * 16 + (l & 15);
                    ldm_x4(Hb + (row * SH + k0 + ((l >> 4) << 3)) * 2,
                           af[i][0], af[i][1], af[i][2], af[i][3]);
                }
                uint32_t bf[2];
                {
                    uint32_t rn = wn2 * 8 + (l & 7);
                    ldm_x2(W2b + (rn * SH + k0 + (((l >> 3) & 1) << 3)) * 2, bf[0], bf[1]);
                }
#pragma unroll
                for (int i = 0; i < 2; ++i) mma16816(ac2[i], af[i], bf);
            }
            // writeback straight from accumulators (skip ch3 — exact path above)
#pragma unroll
            for (int i = 0; i < 2; ++i)
#pragma unroll
                for (int e = 0; e < 4; ++e) {
                    const int m  = wm2 * 32 + i * 16 + q + (e >> 1) * 8;
                    const int ch = wn2 * 8 + cb + (e & 1);
                    if (ch == 3) continue;
                    const float f = sFire[m];
                    const uint32_t idx = (((uint32_t)b * CHN + ch) << 16)
                                       + ((uint32_t)y << 8) + (xb + m);
                    g_x2[idx] = sXC[m * 33 + ch] + ac2[i][e] * f;
                }
        }
        // no end-of-tile barrier: next iteration's B1 provides the ordering
    }
}

// ---------------------------------------------------------------------------
__global__ __launch_bounds__(256)
void nca_mask_kernel(const float* __restrict__ x, float* __restrict__ out)
{
    int gid = blockIdx.x * 256 + threadIdx.x;
    int b  = gid >> 16;
    int y  = (gid >> 8) & 255;
    int xx = gid & 255;

    const float* xc  = x    + (((uint32_t)b * CHN + 3) << 16);
    const float* x2c = g_x2 + (((uint32_t)b * CHN + 3) << 16);

    float m1 = -1e30f, m2 = -1e30f;
    int y0 = y > 0 ? y - 1 : 0, y1 = y < HW - 1 ? y + 1 : HW - 1;
    int x0 = xx > 0 ? xx - 1 : 0, x1 = xx < HW - 1 ? xx + 1 : HW - 1;
    for (int yy = y0; yy <= y1; ++yy)
        for (int xw = x0; xw <= x1; ++xw) {
            m1 = fmaxf(m1, xc[yy * HW + xw]);
            m2 = fmaxf(m2, x2c[yy * HW + xw]);
        }
    float life = (m1 > 0.1f && m2 > 0.1f) ? 1.f : 0.f;

    uint32_t base = ((uint32_t)b * CHN << 16) + ((uint32_t)y << 8) + xx;
#pragma unroll
    for (int o = 0; o < CHN; ++o)
        out[base + ((uint32_t)o << 16)] = g_x2[base + ((uint32_t)o << 16)] * life;
}

// ---------------------------------------------------------------------------
extern "C" void kernel_launch(void* const* d_in, const int* in_sizes, int n_in,
                              void* d_out, int out_size)
{
    const float* x  = (const float*)d_in[0];
    const float* ru = (const float*)d_in[1];
    const float* W1 = (const float*)d_in[2];
    const float* b1 = (const float*)d_in[3];
    const float* W2 = (const float*)d_in[4];
    float* out = (float*)d_out;

    cudaFuncSetAttribute(nca_mma_kernel,
                         cudaFuncAttributeMaxDynamicSharedMemorySize, SMEM_TOTAL);
    nca_mma_kernel<<<NCTAS, 256, SMEM_TOTAL>>>(x, ru, W1, b1, W2);
    nca_mask_kernel<<<(8 * HW * HW) / 256, 256>>>(x, out);
}

// round 12
// speedup vs baseline: 1.1808x; 1.0013x over previous
#include <cuda_runtime.h>
#include <cuda_bf16.h>
#include <cstdint>

#define HW 256
#define CHN 32
#define HID 256
#define K1 96
#define SP 104          // row stride (bf16 elems) for P / W1
#define SH 264          // row stride (bf16 elems) for H / W2
#define TM 64           // pixels per tile
#define NTILES 8192
#define NCTAS 148

// smem byte offsets
#define OFF_W1H 0
#define OFF_W1M (OFF_W1H + HID*SP*2)
#define OFF_W2H (OFF_W1M + HID*SP*2)
#define OFF_B1  (OFF_W2H + CHN*SH*2)
#define OFF_W2R3 (OFF_B1 + HID*4)
#define OFF_PH  (OFF_W2R3 + HID*4)
#define OFF_PM  (OFF_PH + TM*SP*2)
#define OFF_H   (OFF_PM + TM*SP*2)
#define OFF_RB  (OFF_H + TM*SH*2 + 16)        // 185872 (16B aligned)
#define RB_CH   220
#define RB_ROW  72
#define OFF_XC  (OFF_RB + CHN*RB_CH*4)        // 214032
#define OFF_RU  (OFF_XC + TM*33*4)            // 222480 (16B aligned)
#define OFF_C3P (OFF_RU + TM*4)               // 222736
#define OFF_FIRE (OFF_C3P + 4*TM*4)           // 223760
#define SMEM_TOTAL (OFF_FIRE + TM*4)          // 224016

__device__ float g_x2[8 * CHN * HW * HW];

__device__ __forceinline__ uint32_t smem_u32(const void* p) {
    uint32_t a;
    asm("{ .reg .u64 t; cvta.to.shared.u64 t, %1; cvt.u32.u64 %0, t; }" : "=r"(a) : "l"(p));
    return a;
}
__device__ __forceinline__ void ldm_x4(uint32_t a, uint32_t& r0, uint32_t& r1, uint32_t& r2, uint32_t& r3) {
    asm volatile("ldmatrix.sync.aligned.m8n8.x4.shared.b16 {%0,%1,%2,%3}, [%4];"
                 : "=r"(r0), "=r"(r1), "=r"(r2), "=r"(r3) : "r"(a));
}
__device__ __forceinline__ void ldm_x2(uint32_t a, uint32_t& r0, uint32_t& r1) {
    asm volatile("ldmatrix.sync.aligned.m8n8.x2.shared.b16 {%0,%1}, [%2];"
                 : "=r"(r0), "=r"(r1) : "r"(a));
}
__device__ __forceinline__ void mma16816(float* d, const uint32_t* a, const uint32_t* b) {
    asm volatile("mma.sync.aligned.m16n8k16.row.col.f32.bf16.bf16.f32 "
                 "{%0,%1,%2,%3}, {%4,%5,%6,%7}, {%8,%9}, {%0,%1,%2,%3};"
                 : "+f"(d[0]), "+f"(d[1]), "+f"(d[2]), "+f"(d[3])
                 : "r"(a[0]), "r"(a[1]), "r"(a[2]), "r"(a[3]), "r"(b[0]), "r"(b[1]));
}
__device__ __forceinline__ uint32_t pack2(float lo, float hi) {
    __nv_bfloat162 t = __floats2bfloat162_rn(lo, hi);
    return *(uint32_t*)&t;
}
__device__ __forceinline__ uint32_t pkraw(__nv_bfloat16 lo, __nv_bfloat16 hi) {
    return ((uint32_t)__bfloat16_as_ushort(hi) << 16) | (uint32_t)__bfloat16_as_ushort(lo);
}

// ---------------------------------------------------------------------------
__global__ __launch_bounds__(256, 1)
void nca_mma_kernel(const float* __restrict__ x, const float* __restrict__ ru,
                    const float* __restrict__ W1, const float* __restrict__ b1,
                    const float* __restrict__ W2)
{
    extern __shared__ char smem[];
    const uint32_t sbase = smem_u32(smem);
    const int tid = threadIdx.x;
    const int wid = tid >> 5;
    const int l   = tid & 31;

    // ---- one-time: weights into smem
    for (int idx = tid; idx < HID * K1; idx += 256) {
        int n = idx / K1, k = idx - n * K1;
        float v = W1[idx];
        __nv_bfloat16 h = __float2bfloat16_rn(v);
        float r = v - __bfloat162float(h);
        *(__nv_bfloat16*)(smem + OFF_W1H + (n * SP + k) * 2) = h;
        *(__nv_bfloat16*)(smem + OFF_W1M + (n * SP + k) * 2) = __float2bfloat16_rn(r);
    }
    for (int idx = tid; idx < CHN * HID; idx += 256) {
        int n = idx >> 8, k = idx & 255;
        *(__nv_bfloat16*)(smem + OFF_W2H + (n * SH + k) * 2) = __float2bfloat16_rn(W2[idx]);
    }
    for (int idx = tid; idx < HID; idx += 256) {
        ((float*)(smem + OFF_B1))[idx]   = b1[idx];
        ((float*)(smem + OFF_W2R3))[idx] = W2[3 * HID + idx];
    }
    __syncthreads();

    const float* b1f   = (const float*)(smem + OFF_B1);
    const float* w2r3  = (const float*)(smem + OFF_W2R3);
    float*       sC3P  = (float*)(smem + OFF_C3P);   // [4][64] per-wn partials
    const float* rb    = (const float*)(smem + OFF_RB);
    float*       sXC   = (float*)(smem + OFF_XC);
    const float* sRU   = (const float*)(smem + OFF_RU);
    float*       sFire = (float*)(smem + OFF_FIRE);

    const int q  = l >> 2;
    const int cb = 2 * (l & 3);

    // ---- tile-invariant prefetch chunk geometry (x: 1728 chunks, ru: 16 chunks) ----
    int pfRow[7], pfCx[7];
    uint32_t pfDst[7], pfChO[7];
    int nPf = 0;
    for (int k = 0; k < 7; ++k) {
        int i = tid + 256 * k;
        if (i < 1728) {
            int ch  = i / 54;
            int rem = i - ch * 54;
            int row = rem / 18;
            int cx  = rem - row * 18;
            pfRow[nPf] = row;
            pfCx[nPf]  = cx;
            pfChO[nPf] = ((uint32_t)ch << 16);
            pfDst[nPf] = sbase + OFF_RB + (uint32_t)(ch * RB_CH + row * RB_ROW + cx * 4) * 4;
            ++nPf;
        } else if (i < 1744) {
            int cx = i - 1728;
            pfRow[nPf] = 3;                    // sentinel: ru chunk
            pfCx[nPf]  = cx;
            pfChO[nPf] = 0;
            pfDst[nPf] = sbase + OFF_RU + (uint32_t)cx * 16;
            ++nPf;
        }
    }

    auto prefetch = [&](int tile) {
        const int b  = tile >> 10;
        const int rr = tile & 1023;
        const int y  = rr >> 2;
        const int xb = (rr & 3) << 6;
        const float* xim = x + (uint32_t)b * (CHN * HW * HW);
        const float* rurow = ru + (((uint32_t)b << 16) + ((uint32_t)y << 8) + xb);
        for (int k = 0; k < nPf; ++k) {
            if (pfRow[k] == 3) {
                const float* src = rurow + pfCx[k] * 4;
                asm volatile("cp.async.ca.shared.global [%0], [%1], 16, 16;"
                             :: "r"(pfDst[k]), "l"(src));
            } else {
                const int srow = y - 1 + pfRow[k];
                const int px0  = xb - 4 + pfCx[k] * 4;
                const bool ok = (srow >= 0) & (srow < HW) & (px0 >= 0) & (px0 <= HW - 4);
                const float* src = xim + pfChO[k] + ((uint32_t)(srow & 255) << 8) + (px0 & 255);
                const int sz = ok ? 16 : 0;
                asm volatile("cp.async.ca.shared.global [%0], [%1], 16, %2;"
                             :: "r"(pfDst[k]), "l"(src), "r"(sz));
            }
        }
        asm volatile("cp.async.commit_group;" ::: "memory");
    };

    if (blockIdx.x < NTILES) prefetch(blockIdx.x);

    for (int tile = blockIdx.x; tile < NTILES; tile += NCTAS) {
        const int b  = tile >> 10;
        const int rr = tile & 1023;
        const int y  = rr >> 2;
        const int xb = (rr & 3) << 6;

        asm volatile("cp.async.wait_group 0;" ::: "memory");
        __syncthreads();                                    // B1

        // grab this tile's ru before prefetch (at B2) can overwrite the slot;
        // stash fire in sFire for the post-B3 register writeback
        const float myRu = sRU[tid & 63];
        const float fire = (myRu <= 0.5f) ? 1.f : 0.f;
        if (tid < TM) sFire[tid] = fire;

        // ============ Phase A: perceive from RB, packed-pair split stores ============
        {
            const int c0 = wid * 4;
            uint32_t* pH = (uint32_t*)(smem + OFF_PH);
            uint32_t* pM = (uint32_t*)(smem + OFF_PM);
#pragma unroll
            for (int half = 0; half < 2; ++half) {
                const int pp = l + 32 * half;
                const int wbase = pp * 52 + 6 * wid;
#pragma unroll
                for (int cp = 0; cp < 2; ++cp) {
                    float vv[6];
#pragma unroll
                    for (int u = 0; u < 2; ++u) {
                        const int c = c0 + 2 * cp + u;
                        const float* r0 = rb + c * RB_CH + (pp + 3);
                        const float* r1 = r0 + RB_ROW;
                        const float* r2 = r1 + RB_ROW;
                        float a00 = r0[0], a01 = r0[1], a02 = r0[2];
                        float a10 = r1[0], a11 = r1[1], a12 = r1[2];
                        float a20 = r2[0], a21 = r2[1], a22 = r2[2];
                        vv[3 * u]     = a11;
                        vv[3 * u + 1] = ((a02 - a00) + 2.f * (a12 - a10) + (a22 - a20)) * 0.125f;
                        vv[3 * u + 2] = ((a20 - a00) + 2.f * (a21 - a01) + (a22 - a02)) * 0.125f;
                        sXC[pp * 33 + c] = a11;
                    }
                    __nv_bfloat16 h[6];
                    uint32_t mw[3];
#pragma unroll
                    for (int j = 0; j < 3; ++j) {
                        h[2*j]   = __float2bfloat16_rn(vv[2*j]);
                        h[2*j+1] = __float2bfloat16_rn(vv[2*j+1]);
                        __nv_bfloat16 m0 = __float2bfloat16_rn(vv[2*j]   - __bfloat162float(h[2*j]));
                        __nv_bfloat16 m1 = __float2bfloat16_rn(vv[2*j+1] - __bfloat162float(h[2*j+1]));
                        mw[j] = pkraw(m0, m1);
                    }
                    const int wofs = wbase + 3 * cp;
                    pH[wofs]     = pkraw(h[0], h[1]);
                    pH[wofs + 1] = pkraw(h[2], h[3]);
                    pH[wofs + 2] = pkraw(h[4], h[5]);
                    pM[wofs]     = mw[0];
                    pM[wofs + 1] = mw[1];
                    pM[wofs + 2] = mw[2];
                }
            }
        }
        __syncthreads();                                    // B2

        if (tile + NCTAS < NTILES) prefetch(tile + NCTAS);

        // ============ Phase B: GEMM1 (M64 x N256 x K96), fragment-reuse, 3 products ============
        const int wm = wid >> 2, wn = wid & 3;
        float acc[2][8][4];
#pragma unroll
        for (int i = 0; i < 2; ++i)
#pragma unroll
            for (int j = 0; j < 8; ++j)
#pragma unroll
                for (int e = 0; e < 4; ++e) acc[i][j][e] = 0.f;
        {
            const int gi = l >> 3;
            const int gj = (gi >> 1) * 8 + (l & 7);
            const int gk = (gi & 1) << 3;
            const uint32_t AH = sbase + OFF_PH, AM = sbase + OFF_PM;
            const uint32_t BH = sbase + OFF_W1H, BM = sbase + OFF_W1M;
#pragma unroll
            for (int ks = 0; ks < 6; ++ks) {
                const int k0 = ks * 16;
                const uint32_t aoff = ((wm * 32 + (l & 15)) * SP + k0 + ((l >> 4) << 3)) * 2;
                const uint32_t boff = ((wn * 64 + gj) * SP + k0 + gk) * 2;
                uint32_t afH[2][4], afM[2][4];
#pragma unroll
                for (int i = 0; i < 2; ++i) {
                    ldm_x4(AH + aoff + i * (16 * SP * 2),
                           afH[i][0], afH[i][1], afH[i][2], afH[i][3]);
                    ldm_x4(AM + aoff + i * (16 * SP * 2),
                           afM[i][0], afM[i][1], afM[i][2], afM[i][3]);
                }
                uint32_t bfH[8][2], bfM[8][2];
#pragma unroll
                for (int jp = 0; jp < 4; ++jp) {
                    ldm_x4(BH + boff + jp * (16 * SP * 2),
                           bfH[2*jp][0], bfH[2*jp][1], bfH[2*jp+1][0], bfH[2*jp+1][1]);
                    ldm_x4(BM + boff + jp * (16 * SP * 2),
                           bfM[2*jp][0], bfM[2*jp][1], bfM[2*jp+1][0], bfM[2*jp+1][1]);
                }
#pragma unroll
                for (int i = 0; i < 2; ++i)
#pragma unroll
                    for (int j = 0; j < 8; ++j) {
                        mma16816(acc[i][j], afH[i], bfH[j]);   // hh
                        mma16816(acc[i][j], afH[i], bfM[j]);   // hm
                        mma16816(acc[i][j], afM[i], bfH[j]);   // mh
                    }
            }
        }

        // ============ Phase C: epilogue1 — bias+relu, pack H, ch3 partials ============
        {
            float p3[2][2] = {{0.f, 0.f}, {0.f, 0.f}};
#pragma unroll
            for (int i = 0; i < 2; ++i) {
                const int m0 = wm * 32 + i * 16 + q;
#pragma unroll
                for (int j = 0; j < 8; ++j) {
                    const int n0 = wn * 64 + j * 8 + cb;
                    float h0 = fmaxf(acc[i][j][0] + b1f[n0],     0.f);
                    float h1 = fmaxf(acc[i][j][1] + b1f[n0 + 1], 0.f);
                    float h2 = fmaxf(acc[i][j][2] + b1f[n0],     0.f);
                    float h3 = fmaxf(acc[i][j][3] + b1f[n0 + 1], 0.f);
                    p3[i][0] += h0 * w2r3[n0] + h1 * w2r3[n0 + 1];
                    p3[i][1] += h2 * w2r3[n0] + h3 * w2r3[n0 + 1];
                    *(uint32_t*)(smem + OFF_H + (m0 * SH + n0) * 2)       = pack2(h0, h1);
                    *(uint32_t*)(smem + OFF_H + ((m0 + 8) * SH + n0) * 2) = pack2(h2, h3);
                }
            }
#pragma unroll
            for (int i = 0; i < 2; ++i)
#pragma unroll
                for (int r = 0; r < 2; ++r) {
                    float v = p3[i][r];
                    v += __shfl_xor_sync(0xFFFFFFFF, v, 1);
                    v += __shfl_xor_sync(0xFFFFFFFF, v, 2);
                    if ((l & 3) == 0)
                        sC3P[wn * TM + wm * 32 + i * 16 + q + r * 8] = v;
                }
        }
        __syncthreads();                                    // B3

        // ch3 finalize: exact x2[ch3] from sXC + summed partials
        if (tid < TM) {
            const int m = tid, px = xb + m;
            const float p3sum = sC3P[m] + sC3P[TM + m] + sC3P[2 * TM + m] + sC3P[3 * TM + m];
            const uint32_t i3 = (((uint32_t)b * CHN + 3) << 16) + ((uint32_t)y << 8) + px;
            g_x2[i3] = sXC[m * 33 + 3] + p3sum * fire;
        }

        // ============ Phase D: GEMM2 (M64 x N32 x K256, full-K per warp) +
        //              direct register writeback (no sPart, no extra barrier) ============
        {
            const int wm2 = wid & 1, wn2 = wid >> 1;        // 2M x 4N
            float ac2[2][4];
#pragma unroll
            for (int i = 0; i < 2; ++i)
#pragma unroll
                for (int e = 0; e < 4; ++e) ac2[i][e] = 0.f;
            const uint32_t Hb = sbase + OFF_H, W2b = sbase + OFF_W2H;
#pragma unroll
            for (int ks = 0; ks < 16; ++ks) {
                const int k0 = ks * 16;
                uint32_t af[2][4];
#pragma unroll
                for (int i = 0; i < 2; ++i) {
                    uint32_t row = wm2 * 32 + i * 16 + (l & 15);
                    ldm_x4(Hb + (row * SH + k0 + ((l >> 4) << 3)) * 2,
                           af[i][0], af[i][1], af[i][2], af[i][3]);
                }
                uint32_t bf[2];
                {
                    uint32_t rn = wn2 * 8 + (l & 7);
                    ldm_x2(W2b + (rn * SH + k0 + (((l >> 3) & 1) << 3)) * 2, bf[0], bf[1]);
                }
#pragma unroll
                for (int i = 0; i < 2; ++i) mma16816(ac2[i], af[i], bf);
            }
            // writeback straight from accumulators (skip ch3 — exact path above)
#pragma unroll
            for (int i = 0; i < 2; ++i)
#pragma unroll
                for (int e = 0; e < 4; ++e) {
                    const int m  = wm2 * 32 + i * 16 + q + (e >> 1) * 8;
                    const int ch = wn2 * 8 + cb + (e & 1);
                    if (ch == 3) continue;
                    const float f = sFire[m];
                    const uint32_t idx = (((uint32_t)b * CHN + ch) << 16)
                                       + ((uint32_t)y << 8) + (xb + m);
                    g_x2[idx] = sXC[m * 33 + ch] + ac2[i][e] * f;
                }
        }
        // no end-of-tile barrier: next iteration's B1 provides the ordering
    }
}

// ---------------------------------------------------------------------------
__global__ __launch_bounds__(256)
void nca_mask_kernel(const float* __restrict__ x, float* __restrict__ out)
{
    int gid = blockIdx.x * 256 + threadIdx.x;
    int b  = gid >> 16;
    int y  = (gid >> 8) & 255;
    int xx = gid & 255;

    const float* xc  = x    + (((uint32_t)b * CHN + 3) << 16);
    const float* x2c = g_x2 + (((uint32_t)b * CHN + 3) << 16);

    float m1 = -1e30f, m2 = -1e30f;
    int y0 = y > 0 ? y - 1 : 0, y1 = y < HW - 1 ? y + 1 : HW - 1;
    int x0 = xx > 0 ? xx - 1 : 0, x1 = xx < HW - 1 ? xx + 1 : HW - 1;
    for (int yy = y0; yy <= y1; ++yy)
        for (int xw = x0; xw <= x1; ++xw) {
            m1 = fmaxf(m1, xc[yy * HW + xw]);
            m2 = fmaxf(m2, x2c[yy * HW + xw]);
        }
    float life = (m1 > 0.1f && m2 > 0.1f) ? 1.f : 0.f;

    uint32_t base = ((uint32_t)b * CHN << 16) + ((uint32_t)y << 8) + xx;
#pragma unroll
    for (int o = 0; o < CHN; ++o)
        out[base + ((uint32_t)o << 16)] = g_x2[base + ((uint32_t)o << 16)] * life;
}

// ---------------------------------------------------------------------------
extern "C" void kernel_launch(void* const* d_in, const int* in_sizes, int n_in,
                              void* d_out, int out_size)
{
    const float* x  = (const float*)d_in[0];
    const float* ru = (const float*)d_in[1];
    const float* W1 = (const float*)d_in[2];
    const float* b1 = (const float*)d_in[3];
    const float* W2 = (const float*)d_in[4];
    float* out = (float*)d_out;

    cudaFuncSetAttribute(nca_mma_kernel,
                         cudaFuncAttributeMaxDynamicSharedMemorySize, SMEM_TOTAL);
    nca_mma_kernel<<<NCTAS, 256, SMEM_TOTAL>>>(x, ru, W1, b1, W2);
    nca_mask_kernel<<<(8 * HW * HW) / 256, 256>>>(x, out);
}